// round 15
// baseline (speedup 1.0000x reference)
#include <cuda_runtime.h>
#include <cuda_bf16.h>
#include <math.h>
#include <stdint.h>

// ---------------------------------------------------------------------------
// HistLoss (Round 15): bf16 symmetry-fused 3-GEMM CTA (round-12 winner) with
// KT=96 tiles (fewer barriers), k1 fused into staging, nop launches removed.
//   pair0 = (IyKa)^T Kb ; pair1 = rowrev((IyKa)^T Kba) ;
//   pair2 = rowrev+colrev((IyKb)^T Kba)
// ---------------------------------------------------------------------------

#define NPIX    65536
#define HB      128
#define CELLS   (HB*HB)
#define NIBAT   8           // 2 images * 4 batch
#define NCH     18
#define CHUNK_PX 3648       // 38*96; chunk 17 gets 3520 -> 37 tiles, last padded
#define KT      96          // pixels per staged tile
#define PITCHB  208         // bytes per bin-row (13*16B, odd -> conflict-free)
#define T_BYTES (HB*PITCHB)           // 26624 per operand tile
#define BUF4    (4*T_BYTES)           // 106496: IyKa | Kb | IyKb | Kba
#define STAGE_OFF (2*BUF4)            // 212992 (double buffer)
#define SLOT_B  1536                  // stage slot: a96|b96|ba96|iy96 floats
#define SMEM_TOTAL (STAGE_OFF + 4*SLOT_B)  // 219136 <= 227KB

typedef unsigned long long u64t;

static __device__ float g_partial[24*NCH*CELLS];          // ~28.3 MB
static __device__ float g_bsp[12*64];
static __device__ float g_bst[12*64];
static __device__ float g_bss[12*64];

__device__ __forceinline__ uint32_t smem_u32(const void* p) {
    uint32_t a;
    asm("{ .reg .u64 t; cvta.to.shared.u64 t, %1; cvt.u32.u64 %0, t; }"
        : "=r"(a) : "l"(p));
    return a;
}
__device__ __forceinline__ u64t pack2(float lo, float hi) {
    u64t r; asm("mov.b64 %0, {%1, %2};" : "=l"(r) : "f"(lo), "f"(hi)); return r;
}
__device__ __forceinline__ u64t add2(u64t a, u64t b) {
    u64t d; asm("add.rn.f32x2 %0, %1, %2;" : "=l"(d) : "l"(a), "l"(b)); return d;
}
__device__ __forceinline__ u64t fma2_sq1(u64t a, u64t c) {   // a*a + c
    u64t d; asm("fma.rn.f32x2 %0, %1, %1, %2;" : "=l"(d) : "l"(a), "l"(c)); return d;
}
__device__ __forceinline__ void unpk(u64t v, float& lo, float& hi) {
    asm("mov.b64 {%0, %1}, %2;" : "=f"(lo), "=f"(hi) : "l"(v));
}
__device__ __forceinline__ void lds_2x64(u64t& a, u64t& b, uint32_t addr) {
    asm volatile("ld.shared.v2.b64 {%0, %1}, [%2];" : "=l"(a), "=l"(b) : "r"(addr));
}
__device__ __forceinline__ void sts128(uint32_t a, uint32_t p0, uint32_t p1,
                                       uint32_t p2, uint32_t p3) {
    asm volatile("st.shared.v4.b32 [%0], {%1,%2,%3,%4};"
                 :: "r"(a), "r"(p0), "r"(p1), "r"(p2), "r"(p3) : "memory");
}
__device__ __forceinline__ void ldm_x4(uint32_t& r0, uint32_t& r1,
                                       uint32_t& r2, uint32_t& r3, uint32_t a) {
    asm volatile("ldmatrix.sync.aligned.m8n8.x4.shared.b16 {%0,%1,%2,%3}, [%4];"
                 : "=r"(r0), "=r"(r1), "=r"(r2), "=r"(r3) : "r"(a));
}
__device__ __forceinline__ void mma16816(float* d, uint32_t a0, uint32_t a1,
                                         uint32_t a2, uint32_t a3,
                                         uint32_t b0, uint32_t b1) {
    asm volatile(
        "mma.sync.aligned.m16n8k16.row.col.f32.bf16.bf16.f32 "
        "{%0,%1,%2,%3}, {%4,%5,%6,%7}, {%8,%9}, {%0,%1,%2,%3};"
        : "+f"(d[0]), "+f"(d[1]), "+f"(d[2]), "+f"(d[3])
        : "r"(a0), "r"(a1), "r"(a2), "r"(a3), "r"(b0), "r"(b1));
}

#define EVAL4(xpa, xpb, K0, K1, K2, K3)                                  \
    do {                                                                 \
        u64t qqa = fma2_sq1(add2(xpa, nmus2), one2);                     \
        u64t qqb = fma2_sq1(add2(xpb, nmus2), one2);                     \
        float q0, q1, q2, q3;                                            \
        unpk(qqa, q0, q1); unpk(qqb, q2, q3);                            \
        float q01 = q0 * q1, q23 = q2 * q3, Q = q01 * q23, rcp_;         \
        asm("rcp.approx.ftz.f32 %0, %1;" : "=f"(rcp_) : "f"(Q));         \
        float r01 = rcp_ * q23, r23 = rcp_ * q01;                        \
        K0 = r01 * q1; K1 = r01 * q0; K2 = r23 * q3; K3 = r23 * q2;      \
    } while (0)
#define CVT2(dst, hi, lo) \
    asm("cvt.rn.satfinite.bf16x2.f32 %0, %1, %2;" : "=r"(dst) : "f"(hi), "f"(lo))

// -------------------------------------------------------------------- k2 ---
// 144 CTAs x 512 threads, 1 CTA/SM. CTA = (ibat = bid%8, chunk = bid/8).
// Eval roles: t<128: IyKa row t | t<256: Kb+IyKb row t-128 |
//             t>=256: Kba row (t-256)/2, px-half (t-256)&1 (48 px each).
// MMA: 16 warps; warp w = (g=w&3 rows, h=w>>2 cols) 32x32 tile of EACH GEMM;
// KT=96 -> 6 k16 steps per tile. Pixel staging computes logs/iy inline (k1
// fused); padded pixels get iy=0 so their contributions vanish.
__global__ void __launch_bounds__(512, 1) k2_hist(const float* __restrict__ pred,
                                                  const float* __restrict__ tgt) {
    extern __shared__ char dyn[];
    const int bid   = blockIdx.x;
    const int ibat  = bid % NIBAT;
    const int chunk = bid / NIBAT;
    const int img   = ibat >> 2;
    const int bat   = ibat & 3;
    const float* src = (img ? tgt : pred) + bat * 3 * NPIX;

    const int t    = threadIdx.x;
    const int wid  = t >> 5;
    const int lane = t & 31;
    const uint32_t sbase    = smem_u32(dyn);
    const uint32_t stageAdr = sbase + STAGE_OFF;
    float* stage = (float*)(dyn + STAGE_OFF);   // [4 slots][a|b|ba|iy][96]

    const int start  = chunk * CHUNK_PX;
    const int end    = min(start + CHUNK_PX, NPIX);
    const int cnt    = end - start;
    const int ntiles = (cnt + KT - 1) / KT;     // 38, or 37 (last padded)

    float acc[3][2][4][4];                      // 96 regs
#pragma unroll
    for (int gi = 0; gi < 3; gi++)
#pragma unroll
        for (int mi = 0; mi < 2; mi++)
#pragma unroll
            for (int j = 0; j < 4; j++)
#pragma unroll
                for (int q = 0; q < 4; q++) acc[gi][mi][j][q] = 0.f;

    // ---- eval role config ----
    int grp, row, half;
    if (t < 128)      { grp = 0; row = t;              half = 0; }
    else if (t < 256) { grp = 1; row = t - 128;        half = 0; }
    else              { grp = 2; row = (t - 256) >> 1; half = (t - 256) & 1; }
    const float mus  = (-3.0f + (float)row * (6.0f / 127.0f)) * 50.0f;
    const u64t  nmus2 = pack2(-mus, -mus);
    const u64t  one2  = pack2(1.0f, 1.0f);
    uint32_t dst0, dst1 = 0;
    if (grp == 0)      dst0 = sbase + row * PITCHB;                       // IyKa
    else if (grp == 1) { dst0 = sbase +   T_BYTES + row * PITCHB;         // Kb
                         dst1 = sbase + 2*T_BYTES + row * PITCHB; }       // IyKb
    else               dst0 = sbase + 3*T_BYTES + row * PITCHB + half*96; // Kba
    // stage float offsets (bytes): a=0, b=384, ba=768, iy=1152
    const uint32_t xsOfs = (grp == 0) ? 0u : (grp == 1 ? 384u : 768u + half*192u);

    // ---- mma role config ----
    const int g = wid & 3;
    const int h = wid >> 2;
    const uint32_t aKa = sbase + (g*32 + (lane & 15)) * PITCHB + (lane >> 4) * 16;
    const uint32_t aKb = aKa + 2 * T_BYTES;
    const uint32_t bKb = sbase + T_BYTES + (h*32 + (lane & 15)) * PITCHB
                       + (lane >> 4) * 16;
    const uint32_t bBa = bKb + 2 * T_BYTES;

    // ---- raw pixel -> stage (k1 fused; iy=0 padding) ----
    auto stage_px = [&](int slot, int i, int n) {
        float* st = stage + slot * (SLOT_B / 4);
        if (n < NPIX) {
            float r = fminf(fmaxf(src[n          ], 0.f), 1.f);
            float gg= fminf(fmaxf(src[n +   NPIX ], 0.f), 1.f);
            float b = fminf(fmaxf(src[n + 2*NPIX ], 0.f), 1.f);
            float lr = __logf(r + 1e-6f);
            float lg = __logf(gg + 1e-6f);
            float lb = __logf(b + 1e-6f);
            float av = (lr - lg) * 50.0f;
            float bv = (lr - lb) * 50.0f;
            st[i]        = av;
            st[96 + i]   = bv;
            st[192 + i]  = bv - av;
            st[288 + i]  = sqrtf(fmaf(r, r, fmaf(gg, gg, fmaf(b, b, 1e-6f))));
        } else {
            st[i] = 0.f; st[96 + i] = 0.f; st[192 + i] = 0.f; st[288 + i] = 0.f;
        }
    };

    // prologue: stage px tiles 0,1 (192 threads, 1 px each)
    if (t < 192) {
        const int tl0 = t / 96, i = t % 96;
        stage_px(tl0 & 3, i, start + tl0 * KT + i);
    }
    __syncthreads();

    for (int tl = 0; tl < ntiles; ++tl) {
        // ---- eval(tl) into buf[tl&1] ----
        {
            const uint32_t slot = stageAdr + (tl & 3) * SLOT_B;
            const uint32_t xsA  = slot + xsOfs;
            const uint32_t iyO  = (slot - sbase) + 1152;
            const uint32_t bo   = (tl & 1) * BUF4;
            if (grp == 0) {
#pragma unroll
                for (int pp = 0; pp < 12; ++pp) {
                    u64t xpa, xpb, xpc, xpd;
                    lds_2x64(xpa, xpb, xsA + pp * 32);
                    lds_2x64(xpc, xpd, xsA + pp * 32 + 16);
                    float k0,k1,k2,k3, k4,k5,k6,k7;
                    EVAL4(xpa, xpb, k0,k1,k2,k3);
                    EVAL4(xpc, xpd, k4,k5,k6,k7);
                    float4 w0 = *(const float4*)(dyn + iyO + pp * 32);
                    float4 w1 = *(const float4*)(dyn + iyO + pp * 32 + 16);
                    uint32_t p0,p1,p2,p3;
                    CVT2(p0, k1*w0.y, k0*w0.x); CVT2(p1, k3*w0.w, k2*w0.z);
                    CVT2(p2, k5*w1.y, k4*w1.x); CVT2(p3, k7*w1.w, k6*w1.z);
                    sts128(dst0 + bo + pp * 16, p0, p1, p2, p3);
                }
            } else if (grp == 1) {
#pragma unroll
                for (int pp = 0; pp < 12; ++pp) {
                    u64t xpa, xpb, xpc, xpd;
                    lds_2x64(xpa, xpb, xsA + pp * 32);
                    lds_2x64(xpc, xpd, xsA + pp * 32 + 16);
                    float k0,k1,k2,k3, k4,k5,k6,k7;
                    EVAL4(xpa, xpb, k0,k1,k2,k3);
                    EVAL4(xpc, xpd, k4,k5,k6,k7);
                    uint32_t p0,p1,p2,p3;
                    CVT2(p0, k1, k0); CVT2(p1, k3, k2);
                    CVT2(p2, k5, k4); CVT2(p3, k7, k6);
                    sts128(dst0 + bo + pp * 16, p0, p1, p2, p3);
                    float4 w0 = *(const float4*)(dyn + iyO + pp * 32);
                    float4 w1 = *(const float4*)(dyn + iyO + pp * 32 + 16);
                    CVT2(p0, k1*w0.y, k0*w0.x); CVT2(p1, k3*w0.w, k2*w0.z);
                    CVT2(p2, k5*w1.y, k4*w1.x); CVT2(p3, k7*w1.w, k6*w1.z);
                    sts128(dst1 + bo + pp * 16, p0, p1, p2, p3);
                }
            } else {
#pragma unroll
                for (int pp = 0; pp < 6; ++pp) {
                    u64t xpa, xpb, xpc, xpd;
                    lds_2x64(xpa, xpb, xsA + pp * 32);
                    lds_2x64(xpc, xpd, xsA + pp * 32 + 16);
                    float k0,k1,k2,k3, k4,k5,k6,k7;
                    EVAL4(xpa, xpb, k0,k1,k2,k3);
                    EVAL4(xpc, xpd, k4,k5,k6,k7);
                    uint32_t p0,p1,p2,p3;
                    CVT2(p0, k1, k0); CVT2(p1, k3, k2);
                    CVT2(p2, k5, k4); CVT2(p3, k7, k6);
                    sts128(dst0 + bo + pp * 16, p0, p1, p2, p3);
                }
            }
        }

        // ---- mma(tl-1) on buf[(tl-1)&1]: 6 k16 steps, 3 GEMMs ----
        if (tl > 0) {
            const uint32_t bo = ((tl - 1) & 1) * BUF4;
#pragma unroll
            for (int kk = 0; kk < 6; ++kk) {
                const uint32_t ko = bo + kk * 32;
                uint32_t a0,a1,a2,a3,a4,a5,a6,a7, b0,b1,b2,b3,b4,b5,b6,b7;
                ldm_x4(a0,a1,a2,a3, aKa + ko);
                ldm_x4(a4,a5,a6,a7, aKa + ko + 16 * PITCHB);
                ldm_x4(b0,b1,b2,b3, bKb + ko);
                ldm_x4(b4,b5,b6,b7, bKb + ko + 16 * PITCHB);
                mma16816(acc[0][0][0], a0,a1,a2,a3, b0,b2);
                mma16816(acc[0][0][1], a0,a1,a2,a3, b1,b3);
                mma16816(acc[0][0][2], a0,a1,a2,a3, b4,b6);
                mma16816(acc[0][0][3], a0,a1,a2,a3, b5,b7);
                mma16816(acc[0][1][0], a4,a5,a6,a7, b0,b2);
                mma16816(acc[0][1][1], a4,a5,a6,a7, b1,b3);
                mma16816(acc[0][1][2], a4,a5,a6,a7, b4,b6);
                mma16816(acc[0][1][3], a4,a5,a6,a7, b5,b7);
                ldm_x4(b0,b1,b2,b3, bBa + ko);
                ldm_x4(b4,b5,b6,b7, bBa + ko + 16 * PITCHB);
                mma16816(acc[1][0][0], a0,a1,a2,a3, b0,b2);
                mma16816(acc[1][0][1], a0,a1,a2,a3, b1,b3);
                mma16816(acc[1][0][2], a0,a1,a2,a3, b4,b6);
                mma16816(acc[1][0][3], a0,a1,a2,a3, b5,b7);
                mma16816(acc[1][1][0], a4,a5,a6,a7, b0,b2);
                mma16816(acc[1][1][1], a4,a5,a6,a7, b1,b3);
                mma16816(acc[1][1][2], a4,a5,a6,a7, b4,b6);
                mma16816(acc[1][1][3], a4,a5,a6,a7, b5,b7);
                ldm_x4(a0,a1,a2,a3, aKb + ko);
                ldm_x4(a4,a5,a6,a7, aKb + ko + 16 * PITCHB);
                mma16816(acc[2][0][0], a0,a1,a2,a3, b0,b2);
                mma16816(acc[2][0][1], a0,a1,a2,a3, b1,b3);
                mma16816(acc[2][0][2], a0,a1,a2,a3, b4,b6);
                mma16816(acc[2][0][3], a0,a1,a2,a3, b5,b7);
                mma16816(acc[2][1][0], a4,a5,a6,a7, b0,b2);
                mma16816(acc[2][1][1], a4,a5,a6,a7, b1,b3);
                mma16816(acc[2][1][2], a4,a5,a6,a7, b4,b6);
                mma16816(acc[2][1][3], a4,a5,a6,a7, b5,b7);
            }
        }

        // ---- prefetch px(tl+2) (threads 256-351, 1 px each) ----
        if (t >= 256 && t < 352 && tl + 2 < ntiles) {
            const int i = t - 256;
            stage_px((tl + 2) & 3, i, start + (tl + 2) * KT + i);
        }
        __syncthreads();
    }

    // ---- final mma(ntiles-1) ----
    {
        const uint32_t bo = ((ntiles - 1) & 1) * BUF4;
#pragma unroll
        for (int kk = 0; kk < 6; ++kk) {
            const uint32_t ko = bo + kk * 32;
            uint32_t a0,a1,a2,a3,a4,a5,a6,a7, b0,b1,b2,b3,b4,b5,b6,b7;
            ldm_x4(a0,a1,a2,a3, aKa + ko);
            ldm_x4(a4,a5,a6,a7, aKa + ko + 16 * PITCHB);
            ldm_x4(b0,b1,b2,b3, bKb + ko);
            ldm_x4(b4,b5,b6,b7, bKb + ko + 16 * PITCHB);
            mma16816(acc[0][0][0], a0,a1,a2,a3, b0,b2);
            mma16816(acc[0][0][1], a0,a1,a2,a3, b1,b3);
            mma16816(acc[0][0][2], a0,a1,a2,a3, b4,b6);
            mma16816(acc[0][0][3], a0,a1,a2,a3, b5,b7);
            mma16816(acc[0][1][0], a4,a5,a6,a7, b0,b2);
            mma16816(acc[0][1][1], a4,a5,a6,a7, b1,b3);
            mma16816(acc[0][1][2], a4,a5,a6,a7, b4,b6);
            mma16816(acc[0][1][3], a4,a5,a6,a7, b5,b7);
            ldm_x4(b0,b1,b2,b3, bBa + ko);
            ldm_x4(b4,b5,b6,b7, bBa + ko + 16 * PITCHB);
            mma16816(acc[1][0][0], a0,a1,a2,a3, b0,b2);
            mma16816(acc[1][0][1], a0,a1,a2,a3, b1,b3);
            mma16816(acc[1][0][2], a0,a1,a2,a3, b4,b6);
            mma16816(acc[1][0][3], a0,a1,a2,a3, b5,b7);
            mma16816(acc[1][1][0], a4,a5,a6,a7, b0,b2);
            mma16816(acc[1][1][1], a4,a5,a6,a7, b1,b3);
            mma16816(acc[1][1][2], a4,a5,a6,a7, b4,b6);
            mma16816(acc[1][1][3], a4,a5,a6,a7, b5,b7);
            ldm_x4(a0,a1,a2,a3, aKb + ko);
            ldm_x4(a4,a5,a6,a7, aKb + ko + 16 * PITCHB);
            mma16816(acc[2][0][0], a0,a1,a2,a3, b0,b2);
            mma16816(acc[2][0][1], a0,a1,a2,a3, b1,b3);
            mma16816(acc[2][0][2], a0,a1,a2,a3, b4,b6);
            mma16816(acc[2][0][3], a0,a1,a2,a3, b5,b7);
            mma16816(acc[2][1][0], a4,a5,a6,a7, b0,b2);
            mma16816(acc[2][1][1], a4,a5,a6,a7, b1,b3);
            mma16816(acc[2][1][2], a4,a5,a6,a7, b4,b6);
            mma16816(acc[2][1][3], a4,a5,a6,a7, b5,b7);
        }
    }

    // ---- epilogue: scatter 3 GEMMs to 3 pair-units (with reversals) ----
    float* o0 = g_partial + ((ibat*3 + 0) * NCH + chunk) * CELLS;
    float* o1 = g_partial + ((ibat*3 + 1) * NCH + chunk) * CELLS;
    float* o2 = g_partial + ((ibat*3 + 2) * NCH + chunk) * CELLS;
    const int cofs = 2 * (lane & 3);
#pragma unroll
    for (int mi = 0; mi < 2; ++mi) {
        const int r0 = g * 32 + mi * 16 + (lane >> 2);
#pragma unroll
        for (int j = 0; j < 4; ++j) {
            const int c = h * 32 + j * 8 + cofs;
            float* a4;
            a4 = acc[0][mi][j];                                    // pair0
            *(float2*)(o0 + r0       * HB + c) = make_float2(a4[0], a4[1]);
            *(float2*)(o0 + (r0 + 8) * HB + c) = make_float2(a4[2], a4[3]);
            a4 = acc[1][mi][j];                                    // pair1: rowrev
            *(float2*)(o1 + (127 - r0) * HB + c) = make_float2(a4[0], a4[1]);
            *(float2*)(o1 + (119 - r0) * HB + c) = make_float2(a4[2], a4[3]);
            a4 = acc[2][mi][j];                                    // pair2: both rev
            *(float2*)(o2 + (127 - r0) * HB + (126 - c)) = make_float2(a4[1], a4[0]);
            *(float2*)(o2 + (119 - r0) * HB + (126 - c)) = make_float2(a4[3], a4[2]);
        }
    }
}

// -------------------------------------------------------------------- k3 ---
__global__ void k3_reduce() {
    int blk  = blockIdx.x;
    int bp   = blk >> 6;
    int seg  = blk & 63;
    int cell = seg * 256 + threadIdx.x;
    float p = 0.f, tt = 0.f;
#pragma unroll
    for (int c = 0; c < NCH; c++) {
        p  += g_partial[( bp       * NCH + c) * CELLS + cell];
        tt += g_partial[((12 + bp) * NCH + c) * CELLS + cell];
    }
    float s = sqrtf(p * tt);

    __shared__ float redp[8], redt[8], reds[8];
#pragma unroll
    for (int o = 16; o > 0; o >>= 1) {
        p  += __shfl_down_sync(0xffffffffu, p,  o);
        tt += __shfl_down_sync(0xffffffffu, tt, o);
        s  += __shfl_down_sync(0xffffffffu, s,  o);
    }
    if ((threadIdx.x & 31) == 0) {
        redp[threadIdx.x >> 5] = p;
        redt[threadIdx.x >> 5] = tt;
        reds[threadIdx.x >> 5] = s;
    }
    __syncthreads();
    if (threadIdx.x == 0) {
        float sp = 0.f, st = 0.f, ss = 0.f;
#pragma unroll
        for (int w = 0; w < 8; w++) { sp += redp[w]; st += redt[w]; ss += reds[w]; }
        g_bsp[blk] = sp; g_bst[blk] = st; g_bss[blk] = ss;
    }
}

// ---------------------------------------------------------------- k4final ---
__global__ void k4_final(float* out) {
    int w = threadIdx.x >> 5, lane = threadIdx.x & 31;
    __shared__ float sl[4];
    if (w < 4) {
        float sp = 0.f, st = 0.f, ss = 0.f;
        for (int i = lane; i < 192; i += 32) {
            int blk = (3 * w) * 64 + i;
            sp += g_bsp[blk]; st += g_bst[blk]; ss += g_bss[blk];
        }
#pragma unroll
        for (int o = 16; o > 0; o >>= 1) {
            sp += __shfl_down_sync(0xffffffffu, sp, o);
            st += __shfl_down_sync(0xffffffffu, st, o);
            ss += __shfl_down_sync(0xffffffffu, ss, o);
        }
        if (lane == 0) {
            float Np = sp + 1e-6f, Nt = st + 1e-6f;
            sl[w] = sp / Np + st / Nt - 2.f * ss / sqrtf(Np * Nt);
        }
    }
    __syncthreads();
    if (threadIdx.x == 0) {
        float tot = fmaxf(sl[0] + sl[1] + sl[2] + sl[3], 0.f);
        out[0] = sqrtf(tot) * 0.70710678118654752f * 0.25f;  // (1/sqrt2)/B
    }
}

// ---------------------------------------------------------------------------
extern "C" void kernel_launch(void* const* d_in, const int* in_sizes, int n_in,
                              void* d_out, int out_size) {
    const float* pred = (const float*)d_in[0];
    const float* tgt  = (const float*)d_in[1];
    float* out = (float*)d_out;

    cudaFuncSetAttribute(k2_hist, cudaFuncAttributeMaxDynamicSharedMemorySize,
                         SMEM_TOTAL);

    k2_hist <<<NIBAT * NCH, 512, SMEM_TOTAL>>>(pred, tgt);
    k3_reduce<<<12 * 64, 256>>>();
    k4_final<<<1, 128>>>(out);
}

// round 16
// speedup vs baseline: 1.0861x; 1.0861x over previous
#include <cuda_runtime.h>
#include <cuda_bf16.h>
#include <math.h>
#include <stdint.h>

// ---------------------------------------------------------------------------
// HistLoss (Round 16): byte-exact round-12 winner (symmetry-fused 3-GEMM CTA,
// bf16 mma.sync, KT=64, PITCHB=144) with the nop launches removed.
//   pair0 = (IyKa)^T Kb ; pair1 = rowrev((IyKa)^T Kba) ;
//   pair2 = rowrev+colrev((IyKb)^T Kba)
// ---------------------------------------------------------------------------

#define NPIX    65536
#define HB      128
#define CELLS   (HB*HB)
#define NIBAT   8           // 2 images * 4 batch
#define NCH     18
#define CHUNK_PX 3648       // 57*64; chunk 17 gets 3520 = 55*64 (all full tiles)
#define KT      64          // pixels per staged tile
#define PITCHB  144         // bytes per bin-row (9*16B, conflict-free)
#define T_BYTES (HB*PITCHB)           // 18432 per operand tile
#define BUF4    (4*T_BYTES)           // 73728: IyKa | Kb | IyKb | Kba
#define STAGE_OFF (2*BUF4)            // 147456 (double buffer)
#define SMEM_TOTAL (STAGE_OFF + 4*256*4)   // +4KB staging = 151552

typedef unsigned long long u64t;

static __device__ float g_a      [2*4*NPIX];
static __device__ float g_bdif   [2*4*NPIX];
static __device__ float g_iy     [2*4*NPIX];
static __device__ float g_partial[24*NCH*CELLS];          // ~28.3 MB
static __device__ float g_bsp[12*64];
static __device__ float g_bst[12*64];
static __device__ float g_bss[12*64];

__device__ __forceinline__ uint32_t smem_u32(const void* p) {
    uint32_t a;
    asm("{ .reg .u64 t; cvta.to.shared.u64 t, %1; cvt.u32.u64 %0, t; }"
        : "=r"(a) : "l"(p));
    return a;
}
__device__ __forceinline__ u64t pack2(float lo, float hi) {
    u64t r; asm("mov.b64 %0, {%1, %2};" : "=l"(r) : "f"(lo), "f"(hi)); return r;
}
__device__ __forceinline__ u64t add2(u64t a, u64t b) {
    u64t d; asm("add.rn.f32x2 %0, %1, %2;" : "=l"(d) : "l"(a), "l"(b)); return d;
}
__device__ __forceinline__ u64t fma2_sq1(u64t a, u64t c) {   // a*a + c
    u64t d; asm("fma.rn.f32x2 %0, %1, %1, %2;" : "=l"(d) : "l"(a), "l"(c)); return d;
}
__device__ __forceinline__ void unpk(u64t v, float& lo, float& hi) {
    asm("mov.b64 {%0, %1}, %2;" : "=f"(lo), "=f"(hi) : "l"(v));
}
__device__ __forceinline__ void lds_2x64(u64t& a, u64t& b, uint32_t addr) {
    asm volatile("ld.shared.v2.b64 {%0, %1}, [%2];" : "=l"(a), "=l"(b) : "r"(addr));
}
__device__ __forceinline__ void sts128(uint32_t a, uint32_t p0, uint32_t p1,
                                       uint32_t p2, uint32_t p3) {
    asm volatile("st.shared.v4.b32 [%0], {%1,%2,%3,%4};"
                 :: "r"(a), "r"(p0), "r"(p1), "r"(p2), "r"(p3) : "memory");
}
__device__ __forceinline__ void ldm_x4(uint32_t& r0, uint32_t& r1,
                                       uint32_t& r2, uint32_t& r3, uint32_t a) {
    asm volatile("ldmatrix.sync.aligned.m8n8.x4.shared.b16 {%0,%1,%2,%3}, [%4];"
                 : "=r"(r0), "=r"(r1), "=r"(r2), "=r"(r3) : "r"(a));
}
__device__ __forceinline__ void mma16816(float* d, uint32_t a0, uint32_t a1,
                                         uint32_t a2, uint32_t a3,
                                         uint32_t b0, uint32_t b1) {
    asm volatile(
        "mma.sync.aligned.m16n8k16.row.col.f32.bf16.bf16.f32 "
        "{%0,%1,%2,%3}, {%4,%5,%6,%7}, {%8,%9}, {%0,%1,%2,%3};"
        : "+f"(d[0]), "+f"(d[1]), "+f"(d[2]), "+f"(d[3])
        : "r"(a0), "r"(a1), "r"(a2), "r"(a3), "r"(b0), "r"(b1));
}

#define EVAL4(xpa, xpb, K0, K1, K2, K3)                                  \
    do {                                                                 \
        u64t qqa = fma2_sq1(add2(xpa, nmus2), one2);                     \
        u64t qqb = fma2_sq1(add2(xpb, nmus2), one2);                     \
        float q0, q1, q2, q3;                                            \
        unpk(qqa, q0, q1); unpk(qqb, q2, q3);                            \
        float q01 = q0 * q1, q23 = q2 * q3, Q = q01 * q23, rcp_;         \
        asm("rcp.approx.ftz.f32 %0, %1;" : "=f"(rcp_) : "f"(Q));         \
        float r01 = rcp_ * q23, r23 = rcp_ * q01;                        \
        K0 = r01 * q1; K1 = r01 * q0; K2 = r23 * q3; K3 = r23 * q2;      \
    } while (0)
#define CVT2(dst, hi, lo) \
    asm("cvt.rn.satfinite.bf16x2.f32 %0, %1, %2;" : "=r"(dst) : "f"(hi), "f"(lo))

// -------------------------------------------------------------------- k1 ---
__global__ void k1_prep(const float* __restrict__ pred,
                        const float* __restrict__ tgt) {
    int id  = blockIdx.x * blockDim.x + threadIdx.x;      // 524288 threads
    int img = id >> 18;
    int rem = id & ((1 << 18) - 1);
    int bat = rem >> 16;
    int n   = rem & (NPIX - 1);
    const float* src = (img ? tgt : pred) + bat * 3 * NPIX;
    float r = fminf(fmaxf(src[n          ], 0.f), 1.f);
    float g = fminf(fmaxf(src[n +   NPIX ], 0.f), 1.f);
    float b = fminf(fmaxf(src[n + 2*NPIX ], 0.f), 1.f);
    g_iy[id]   = sqrtf(fmaf(r, r, fmaf(g, g, fmaf(b, b, 1e-6f))));
    float lr = logf(r + 1e-6f);
    float lg = logf(g + 1e-6f);
    float lb = logf(b + 1e-6f);
    g_a   [id] = lr - lg;
    g_bdif[id] = lr - lb;
}

// -------------------------------------------------------------------- k2 ---
// 144 CTAs x 512 threads, 1 CTA/SM. CTA = (ibat = bid%8, chunk = bid/8).
// Eval roles: t<128: IyKa row t | t<256: Kb+IyKb row t-128 |
//             t>=256: Kba row (t-256)/2, px-half (t-256)&1.
// MMA: 16 warps; warp w = (g=w&3 rows, h=w>>2 cols) 32x32 tile of EACH GEMM.
__global__ void __launch_bounds__(512, 1) k2_hist() {
    extern __shared__ char dyn[];
    const int bid   = blockIdx.x;
    const int ibat  = bid % NIBAT;
    const int chunk = bid / NIBAT;
    const int off   = ibat * NPIX;

    const int t    = threadIdx.x;
    const int wid  = t >> 5;
    const int lane = t & 31;
    const uint32_t sbase    = smem_u32(dyn);
    const uint32_t stageAdr = sbase + STAGE_OFF;
    float* stage = (float*)(dyn + STAGE_OFF);   // [4][4][64]: a,b,ba,iy

    const int start  = chunk * CHUNK_PX;
    const int end    = min(start + CHUNK_PX, NPIX);
    const int ntiles = (end - start) / KT;      // 57 or 55, exact

    float acc[3][2][4][4];                      // 96 regs
#pragma unroll
    for (int gi = 0; gi < 3; gi++)
#pragma unroll
        for (int mi = 0; mi < 2; mi++)
#pragma unroll
            for (int j = 0; j < 4; j++)
#pragma unroll
                for (int q = 0; q < 4; q++) acc[gi][mi][j][q] = 0.f;

    // ---- eval role config ----
    int grp, row, half;
    if (t < 128)      { grp = 0; row = t;            half = 0; }
    else if (t < 256) { grp = 1; row = t - 128;      half = 0; }
    else              { grp = 2; row = (t - 256) >> 1; half = (t - 256) & 1; }
    const float mus  = (-3.0f + (float)row * (6.0f / 127.0f)) * 50.0f;
    const u64t  nmus2 = pack2(-mus, -mus);
    const u64t  one2  = pack2(1.0f, 1.0f);
    uint32_t dst0, dst1 = 0;
    if (grp == 0)      dst0 = sbase + row * PITCHB;                       // IyKa
    else if (grp == 1) { dst0 = sbase +   T_BYTES + row * PITCHB;         // Kb
                         dst1 = sbase + 2*T_BYTES + row * PITCHB; }       // IyKb
    else               dst0 = sbase + 3*T_BYTES + row * PITCHB + half*64; // Kba
    const uint32_t xsOfs = (grp == 0) ? 0u : (grp == 1 ? 256u : 512u + half*128u);

    // ---- mma role config ----
    const int g = wid & 3;
    const int h = wid >> 2;
    const uint32_t aKa = sbase + (g*32 + (lane & 15)) * PITCHB + (lane >> 4) * 16;
    const uint32_t aKb = aKa + 2 * T_BYTES;
    const uint32_t bKb = sbase + T_BYTES + (h*32 + (lane & 15)) * PITCHB
                       + (lane >> 4) * 16;
    const uint32_t bBa = bKb + 2 * T_BYTES;

    // prologue: stage px(0), px(1)
    if (t < 128) {
        const int tl0 = t >> 6, i = t & 63;
        float* st = stage + tl0 * 256;
        const int gi = off + start + tl0 * KT + i;
        float av = g_a[gi], bv = g_bdif[gi];
        st[i]        = av * 50.0f;
        st[64 + i]   = bv * 50.0f;
        st[128 + i]  = (bv - av) * 50.0f;
        st[192 + i]  = g_iy[gi];
    }
    __syncthreads();

    for (int tl = 0; tl < ntiles; ++tl) {
        // ---- eval(tl) into buf[tl&1] ----
        {
            const uint32_t slot = stageAdr + (tl & 3) * 1024;
            const uint32_t xsA  = slot + xsOfs;
            const uint32_t iyO  = (slot - sbase) + 768;
            const uint32_t bo   = (tl & 1) * BUF4;
            if (grp == 0) {
#pragma unroll
                for (int pp = 0; pp < 8; ++pp) {
                    u64t xpa, xpb, xpc, xpd;
                    lds_2x64(xpa, xpb, xsA + pp * 32);
                    lds_2x64(xpc, xpd, xsA + pp * 32 + 16);
                    float k0,k1,k2,k3, k4,k5,k6,k7;
                    EVAL4(xpa, xpb, k0,k1,k2,k3);
                    EVAL4(xpc, xpd, k4,k5,k6,k7);
                    float4 w0 = *(const float4*)(dyn + iyO + pp * 32);
                    float4 w1 = *(const float4*)(dyn + iyO + pp * 32 + 16);
                    uint32_t p0,p1,p2,p3;
                    CVT2(p0, k1*w0.y, k0*w0.x); CVT2(p1, k3*w0.w, k2*w0.z);
                    CVT2(p2, k5*w1.y, k4*w1.x); CVT2(p3, k7*w1.w, k6*w1.z);
                    sts128(dst0 + bo + pp * 16, p0, p1, p2, p3);
                }
            } else if (grp == 1) {
#pragma unroll
                for (int pp = 0; pp < 8; ++pp) {
                    u64t xpa, xpb, xpc, xpd;
                    lds_2x64(xpa, xpb, xsA + pp * 32);
                    lds_2x64(xpc, xpd, xsA + pp * 32 + 16);
                    float k0,k1,k2,k3, k4,k5,k6,k7;
                    EVAL4(xpa, xpb, k0,k1,k2,k3);
                    EVAL4(xpc, xpd, k4,k5,k6,k7);
                    uint32_t p0,p1,p2,p3;
                    CVT2(p0, k1, k0); CVT2(p1, k3, k2);
                    CVT2(p2, k5, k4); CVT2(p3, k7, k6);
                    sts128(dst0 + bo + pp * 16, p0, p1, p2, p3);
                    float4 w0 = *(const float4*)(dyn + iyO + pp * 32);
                    float4 w1 = *(const float4*)(dyn + iyO + pp * 32 + 16);
                    CVT2(p0, k1*w0.y, k0*w0.x); CVT2(p1, k3*w0.w, k2*w0.z);
                    CVT2(p2, k5*w1.y, k4*w1.x); CVT2(p3, k7*w1.w, k6*w1.z);
                    sts128(dst1 + bo + pp * 16, p0, p1, p2, p3);
                }
            } else {
#pragma unroll
                for (int pp = 0; pp < 4; ++pp) {
                    u64t xpa, xpb, xpc, xpd;
                    lds_2x64(xpa, xpb, xsA + pp * 32);
                    lds_2x64(xpc, xpd, xsA + pp * 32 + 16);
                    float k0,k1,k2,k3, k4,k5,k6,k7;
                    EVAL4(xpa, xpb, k0,k1,k2,k3);
                    EVAL4(xpc, xpd, k4,k5,k6,k7);
                    uint32_t p0,p1,p2,p3;
                    CVT2(p0, k1, k0); CVT2(p1, k3, k2);
                    CVT2(p2, k5, k4); CVT2(p3, k7, k6);
                    sts128(dst0 + bo + pp * 16, p0, p1, p2, p3);
                }
            }
        }

        // ---- mma(tl-1) on buf[(tl-1)&1]: 3 GEMMs share fragments ----
        if (tl > 0) {
            const uint32_t bo = ((tl - 1) & 1) * BUF4;
#pragma unroll
            for (int kk = 0; kk < 4; ++kk) {
                const uint32_t ko = bo + kk * 32;
                uint32_t a0,a1,a2,a3,a4,a5,a6,a7, b0,b1,b2,b3,b4,b5,b6,b7;
                ldm_x4(a0,a1,a2,a3, aKa + ko);
                ldm_x4(a4,a5,a6,a7, aKa + ko + 16 * PITCHB);
                ldm_x4(b0,b1,b2,b3, bKb + ko);
                ldm_x4(b4,b5,b6,b7, bKb + ko + 16 * PITCHB);
                mma16816(acc[0][0][0], a0,a1,a2,a3, b0,b2);
                mma16816(acc[0][0][1], a0,a1,a2,a3, b1,b3);
                mma16816(acc[0][0][2], a0,a1,a2,a3, b4,b6);
                mma16816(acc[0][0][3], a0,a1,a2,a3, b5,b7);
                mma16816(acc[0][1][0], a4,a5,a6,a7, b0,b2);
                mma16816(acc[0][1][1], a4,a5,a6,a7, b1,b3);
                mma16816(acc[0][1][2], a4,a5,a6,a7, b4,b6);
                mma16816(acc[0][1][3], a4,a5,a6,a7, b5,b7);
                ldm_x4(b0,b1,b2,b3, bBa + ko);
                ldm_x4(b4,b5,b6,b7, bBa + ko + 16 * PITCHB);
                mma16816(acc[1][0][0], a0,a1,a2,a3, b0,b2);
                mma16816(acc[1][0][1], a0,a1,a2,a3, b1,b3);
                mma16816(acc[1][0][2], a0,a1,a2,a3, b4,b6);
                mma16816(acc[1][0][3], a0,a1,a2,a3, b5,b7);
                mma16816(acc[1][1][0], a4,a5,a6,a7, b0,b2);
                mma16816(acc[1][1][1], a4,a5,a6,a7, b1,b3);
                mma16816(acc[1][1][2], a4,a5,a6,a7, b4,b6);
                mma16816(acc[1][1][3], a4,a5,a6,a7, b5,b7);
                ldm_x4(a0,a1,a2,a3, aKb + ko);
                ldm_x4(a4,a5,a6,a7, aKb + ko + 16 * PITCHB);
                mma16816(acc[2][0][0], a0,a1,a2,a3, b0,b2);
                mma16816(acc[2][0][1], a0,a1,a2,a3, b1,b3);
                mma16816(acc[2][0][2], a0,a1,a2,a3, b4,b6);
                mma16816(acc[2][0][3], a0,a1,a2,a3, b5,b7);
                mma16816(acc[2][1][0], a4,a5,a6,a7, b0,b2);
                mma16816(acc[2][1][1], a4,a5,a6,a7, b1,b3);
                mma16816(acc[2][1][2], a4,a5,a6,a7, b4,b6);
                mma16816(acc[2][1][3], a4,a5,a6,a7, b5,b7);
            }
        }

        // ---- prefetch px(tl+2) (threads 256-319: lightest eval group) ----
        if (t >= 256 && t < 320 && tl + 2 < ntiles) {
            const int i = t - 256;
            float* st = stage + ((tl + 2) & 3) * 256;
            const int gi = off + start + (tl + 2) * KT + i;
            float av = g_a[gi], bv = g_bdif[gi];
            st[i]       = av * 50.0f;
            st[64 + i]  = bv * 50.0f;
            st[128 + i] = (bv - av) * 50.0f;
            st[192 + i] = g_iy[gi];
        }
        __syncthreads();
    }

    // ---- final mma(ntiles-1) ----
    {
        const uint32_t bo = ((ntiles - 1) & 1) * BUF4;
#pragma unroll
        for (int kk = 0; kk < 4; ++kk) {
            const uint32_t ko = bo + kk * 32;
            uint32_t a0,a1,a2,a3,a4,a5,a6,a7, b0,b1,b2,b3,b4,b5,b6,b7;
            ldm_x4(a0,a1,a2,a3, aKa + ko);
            ldm_x4(a4,a5,a6,a7, aKa + ko + 16 * PITCHB);
            ldm_x4(b0,b1,b2,b3, bKb + ko);
            ldm_x4(b4,b5,b6,b7, bKb + ko + 16 * PITCHB);
            mma16816(acc[0][0][0], a0,a1,a2,a3, b0,b2);
            mma16816(acc[0][0][1], a0,a1,a2,a3, b1,b3);
            mma16816(acc[0][0][2], a0,a1,a2,a3, b4,b6);
            mma16816(acc[0][0][3], a0,a1,a2,a3, b5,b7);
            mma16816(acc[0][1][0], a4,a5,a6,a7, b0,b2);
            mma16816(acc[0][1][1], a4,a5,a6,a7, b1,b3);
            mma16816(acc[0][1][2], a4,a5,a6,a7, b4,b6);
            mma16816(acc[0][1][3], a4,a5,a6,a7, b5,b7);
            ldm_x4(b0,b1,b2,b3, bBa + ko);
            ldm_x4(b4,b5,b6,b7, bBa + ko + 16 * PITCHB);
            mma16816(acc[1][0][0], a0,a1,a2,a3, b0,b2);
            mma16816(acc[1][0][1], a0,a1,a2,a3, b1,b3);
            mma16816(acc[1][0][2], a0,a1,a2,a3, b4,b6);
            mma16816(acc[1][0][3], a0,a1,a2,a3, b5,b7);
            mma16816(acc[1][1][0], a4,a5,a6,a7, b0,b2);
            mma16816(acc[1][1][1], a4,a5,a6,a7, b1,b3);
            mma16816(acc[1][1][2], a4,a5,a6,a7, b4,b6);
            mma16816(acc[1][1][3], a4,a5,a6,a7, b5,b7);
            ldm_x4(a0,a1,a2,a3, aKb + ko);
            ldm_x4(a4,a5,a6,a7, aKb + ko + 16 * PITCHB);
            mma16816(acc[2][0][0], a0,a1,a2,a3, b0,b2);
            mma16816(acc[2][0][1], a0,a1,a2,a3, b1,b3);
            mma16816(acc[2][0][2], a0,a1,a2,a3, b4,b6);
            mma16816(acc[2][0][3], a0,a1,a2,a3, b5,b7);
            mma16816(acc[2][1][0], a4,a5,a6,a7, b0,b2);
            mma16816(acc[2][1][1], a4,a5,a6,a7, b1,b3);
            mma16816(acc[2][1][2], a4,a5,a6,a7, b4,b6);
            mma16816(acc[2][1][3], a4,a5,a6,a7, b5,b7);
        }
    }

    // ---- epilogue: scatter 3 GEMMs to 3 pair-units (with reversals) ----
    float* o0 = g_partial + ((ibat*3 + 0) * NCH + chunk) * CELLS;
    float* o1 = g_partial + ((ibat*3 + 1) * NCH + chunk) * CELLS;
    float* o2 = g_partial + ((ibat*3 + 2) * NCH + chunk) * CELLS;
    const int cofs = 2 * (lane & 3);
#pragma unroll
    for (int mi = 0; mi < 2; ++mi) {
        const int r0 = g * 32 + mi * 16 + (lane >> 2);
#pragma unroll
        for (int j = 0; j < 4; ++j) {
            const int c = h * 32 + j * 8 + cofs;
            float* a4;
            a4 = acc[0][mi][j];                                    // pair0
            *(float2*)(o0 + r0       * HB + c) = make_float2(a4[0], a4[1]);
            *(float2*)(o0 + (r0 + 8) * HB + c) = make_float2(a4[2], a4[3]);
            a4 = acc[1][mi][j];                                    // pair1: rowrev
            *(float2*)(o1 + (127 - r0) * HB + c) = make_float2(a4[0], a4[1]);
            *(float2*)(o1 + (119 - r0) * HB + c) = make_float2(a4[2], a4[3]);
            a4 = acc[2][mi][j];                                    // pair2: both rev
            *(float2*)(o2 + (127 - r0) * HB + (126 - c)) = make_float2(a4[1], a4[0]);
            *(float2*)(o2 + (119 - r0) * HB + (126 - c)) = make_float2(a4[3], a4[2]);
        }
    }
}

// -------------------------------------------------------------------- k3 ---
__global__ void k3_reduce() {
    int blk  = blockIdx.x;
    int bp   = blk >> 6;
    int seg  = blk & 63;
    int cell = seg * 256 + threadIdx.x;
    float p = 0.f, tt = 0.f;
#pragma unroll
    for (int c = 0; c < NCH; c++) {
        p  += g_partial[( bp       * NCH + c) * CELLS + cell];
        tt += g_partial[((12 + bp) * NCH + c) * CELLS + cell];
    }
    float s = sqrtf(p * tt);

    __shared__ float redp[8], redt[8], reds[8];
#pragma unroll
    for (int o = 16; o > 0; o >>= 1) {
        p  += __shfl_down_sync(0xffffffffu, p,  o);
        tt += __shfl_down_sync(0xffffffffu, tt, o);
        s  += __shfl_down_sync(0xffffffffu, s,  o);
    }
    if ((threadIdx.x & 31) == 0) {
        redp[threadIdx.x >> 5] = p;
        redt[threadIdx.x >> 5] = tt;
        reds[threadIdx.x >> 5] = s;
    }
    __syncthreads();
    if (threadIdx.x == 0) {
        float sp = 0.f, st = 0.f, ss = 0.f;
#pragma unroll
        for (int w = 0; w < 8; w++) { sp += redp[w]; st += redt[w]; ss += reds[w]; }
        g_bsp[blk] = sp; g_bst[blk] = st; g_bss[blk] = ss;
    }
}

// ---------------------------------------------------------------- k4final ---
__global__ void k4_final(float* out) {
    int w = threadIdx.x >> 5, lane = threadIdx.x & 31;
    __shared__ float sl[4];
    if (w < 4) {
        float sp = 0.f, st = 0.f, ss = 0.f;
        for (int i = lane; i < 192; i += 32) {
            int blk = (3 * w) * 64 + i;
            sp += g_bsp[blk]; st += g_bst[blk]; ss += g_bss[blk];
        }
#pragma unroll
        for (int o = 16; o > 0; o >>= 1) {
            sp += __shfl_down_sync(0xffffffffu, sp, o);
            st += __shfl_down_sync(0xffffffffu, st, o);
            ss += __shfl_down_sync(0xffffffffu, ss, o);
        }
        if (lane == 0) {
            float Np = sp + 1e-6f, Nt = st + 1e-6f;
            sl[w] = sp / Np + st / Nt - 2.f * ss / sqrtf(Np * Nt);
        }
    }
    __syncthreads();
    if (threadIdx.x == 0) {
        float tot = fmaxf(sl[0] + sl[1] + sl[2] + sl[3], 0.f);
        out[0] = sqrtf(tot) * 0.70710678118654752f * 0.25f;  // (1/sqrt2)/B
    }
}

// ---------------------------------------------------------------------------
extern "C" void kernel_launch(void* const* d_in, const int* in_sizes, int n_in,
                              void* d_out, int out_size) {
    const float* pred = (const float*)d_in[0];
    const float* tgt  = (const float*)d_in[1];
    float* out = (float*)d_out;

    cudaFuncSetAttribute(k2_hist, cudaFuncAttributeMaxDynamicSharedMemorySize,
                         SMEM_TOTAL);

    k1_prep <<<2048, 256>>>(pred, tgt);
    k2_hist <<<NIBAT * NCH, 512, SMEM_TOTAL>>>();
    k3_reduce<<<12 * 64, 256>>>();
    k4_final<<<1, 128>>>(out);
}